// round 16
// baseline (speedup 1.0000x reference)
#include <cuda_runtime.h>
#include <cuda_bf16.h>

#define TOKENS 32768
#define DDIM 1024
#define RDIM 48
#define MTILE 128
#define THREADS 256
#define NCTAS (TOKENS / MTILE)   // 256 CTAs, 2 per SM
#define KC 32
#define NCH (DDIM / KC)          // 32 chunks per phase
#define NSTAGE 3

#define XST_F 36                 // fp32 elems/row (144B)
#define WDST 40                  // bf16 elems/row (80B; ldsm conflict-free)
#define WUST 56                  // bf16 elems/row (112B; ldsm conflict-free)
#define YS_STRIDE 52             // bf16
#define H2_STRIDE 52             // bf16

#define XSTG (MTILE * XST_F * 4)         // 18432
#define WSTAGE_B (RDIM * WDST * 2)       // 3840 (>= wu stage 32*112=3584)

// ---- smem layout (bytes): 103232 total -> 2 CTAs/SM ----
#define OFF_XST 0                                  // 3 x-stages: 55296
#define OFF_WST (OFF_XST + NSTAGE * XSTG)          // 3 w-stages: 11520
#define OFF_Y   (OFF_WST + NSTAGE * WSTAGE_B)      // 13312
#define OFF_H2  (OFF_Y + MTILE * YS_STRIDE * 2)    // 13312
#define OFF_A48 (OFF_H2 + MTILE * H2_STRIDE * 2)   // 9216
#define OFF_SGW (OFF_A48 + RDIM * RDIM * 4)        // 192
#define OFF_CB  (OFF_SGW + RDIM * 4)               // 192
#define OFF_C48 (OFF_CB + RDIM * 4)                // 192
#define SMEM_TOTAL (OFF_C48 + RDIM * 4)            // 103232

// ---- global scratch (prep output) ----
__device__ __align__(16) __nv_bfloat16 g_gw[RDIM * DDIM];   // gamma (*) w_down
__device__ __align__(16) __nv_bfloat16 g_wu[DDIM * RDIM];
__device__ float g_sumgw[RDIM];
__device__ float g_cb[RDIM];
__device__ float g_c48[RDIM];
__device__ float g_A48T[RDIM * RDIM];

__device__ __forceinline__ float gelu_exact(float v) {
    return 0.5f * v * (1.0f + erff(v * 0.70710678118654752440f));
}

__device__ __forceinline__ void mma_bf16(float* c, unsigned a0, unsigned a1, unsigned a2,
                                         unsigned a3, unsigned b0, unsigned b1) {
    asm volatile(
        "mma.sync.aligned.m16n8k16.row.col.f32.bf16.bf16.f32 "
        "{%0,%1,%2,%3}, {%4,%5,%6,%7}, {%8,%9}, {%0,%1,%2,%3};\n"
        : "+f"(c[0]), "+f"(c[1]), "+f"(c[2]), "+f"(c[3])
        : "r"(a0), "r"(a1), "r"(a2), "r"(a3), "r"(b0), "r"(b1));
}

__device__ __forceinline__ void ldsm_x4(unsigned* r, unsigned addr) {
    asm volatile("ldmatrix.sync.aligned.m8n8.x4.shared.b16 {%0,%1,%2,%3}, [%4];"
                 : "=r"(r[0]), "=r"(r[1]), "=r"(r[2]), "=r"(r[3]) : "r"(addr));
}

__device__ __forceinline__ unsigned pack2(float a, float b) {
    __nv_bfloat162 p = __floats2bfloat162_rn(a, b);
    return *(unsigned*)&p;
}
__device__ __forceinline__ uint2 pack_bf16x4(float a, float b, float c, float d) {
    uint2 pk;
    pk.x = pack2(a, b);
    pk.y = pack2(c, d);
    return pk;
}

__device__ __forceinline__ void cp16(unsigned dst, const void* src) {
    asm volatile("cp.async.cg.shared.global [%0], [%1], 16;\n" :: "r"(dst), "l"(src));
}
__device__ __forceinline__ void cp_commit() {
    asm volatile("cp.async.commit_group;\n");
}
template <int N>
__device__ __forceinline__ void cp_wait() {
    asm volatile("cp.async.wait_group %0;\n" :: "n"(N));
}

// ============================================================================
// prep: gamma-folded w_down -> bf16, w_up -> bf16, sumgw/cb, collapsed 48x48.
// ============================================================================
__global__ void prep_kernel(const float* __restrict__ gamma, const float* __restrict__ beta,
                            const float* __restrict__ w_down, const float* __restrict__ w_to_mv,
                            const float* __restrict__ w_equi, const float* __restrict__ b_equi,
                            const float* __restrict__ w_from_mv, const float* __restrict__ w_up) {
    int tid = threadIdx.x, lane = tid & 31;
    int gtid = blockIdx.x * blockDim.x + tid;
    int nth = gridDim.x * blockDim.x;
    int gwarp = gtid >> 5;

    if (gwarp < RDIM) {
        int r = gwarp;
        float s = 0.f, cb = 0.f;
        #pragma unroll
        for (int it = 0; it < 8; it++) {
            int d = it * 128 + lane * 4;
            float4 w  = *(const float4*)(w_down + (size_t)r * DDIM + d);
            float4 gv = *(const float4*)(gamma + d);
            float4 bv = *(const float4*)(beta + d);
            uint2 pk = pack_bf16x4(w.x * gv.x, w.y * gv.y, w.z * gv.z, w.w * gv.w);
            *(uint2*)(g_gw + (size_t)r * DDIM + d) = pk;
            __nv_bfloat162 b0 = *(__nv_bfloat162*)&pk.x;
            __nv_bfloat162 b1 = *(__nv_bfloat162*)&pk.y;
            s += __bfloat162float(b0.x) + __bfloat162float(b0.y)
               + __bfloat162float(b1.x) + __bfloat162float(b1.y);
            cb += w.x * bv.x + w.y * bv.y + w.z * bv.z + w.w * bv.w;
        }
        #pragma unroll
        for (int off = 16; off; off >>= 1) {
            s  += __shfl_xor_sync(0xffffffffu, s, off);
            cb += __shfl_xor_sync(0xffffffffu, cb, off);
        }
        if (lane == 0) { g_sumgw[r] = s; g_cb[r] = cb; }
    }
    for (int i = gtid; i < DDIM * RDIM / 4; i += nth) {
        float4 v = ((const float4*)w_up)[i];
        ((uint2*)g_wu)[i] = pack_bf16x4(v.x, v.y, v.z, v.w);
    }
    for (int i = gtid; i < RDIM * RDIM; i += nth) {
        int rp = i / RDIM, r = i - rp * RDIM;
        float a = 0.f;
        #pragma unroll
        for (int m = 0; m < 16; m++) {
            int gidx = (m == 0) ? 0 : (m < 5) ? 1 : (m < 11) ? 2 : (m < 15) ? 3 : 4;
            a += __ldg(w_from_mv + r * 16 + m) * __ldg(w_equi + gidx)
               * __ldg(w_to_mv + m * RDIM + rp);
        }
        g_A48T[i] = a;
    }
    for (int i = gtid; i < RDIM; i += nth)
        g_c48[i] = __ldg(w_from_mv + i * 16) * __ldg(b_equi);
}

// ============================================================================
// Fused kernel: 128-token tiles, 256 threads, 2 CTAs/SM. RACE-FREE pipeline:
// each iteration does wait<1> -> barrier -> issue(kc+2) -> consume(kc), so a
// stage is only overwritten after the barrier that follows everyone's read.
// ============================================================================
__global__ void __launch_bounds__(THREADS, 2) fused_kernel(
    const float* __restrict__ x, const float* __restrict__ scale_p,
    float* __restrict__ out)
{
    extern __shared__ char smem[];
    const unsigned sbase = (unsigned)__cvta_generic_to_shared(smem);
    __nv_bfloat16* y_s  = (__nv_bfloat16*)(smem + OFF_Y);
    __nv_bfloat16* h2_s = (__nv_bfloat16*)(smem + OFF_H2);
    float* A48T_s  = (float*)(smem + OFF_A48);
    float* sumgw_s = (float*)(smem + OFF_SGW);
    float* cb_s    = (float*)(smem + OFF_CB);
    float* c48_s   = (float*)(smem + OFF_C48);

    const int tid = threadIdx.x, lane = tid & 31, warp = tid >> 5;
    const int g = lane >> 2, t4 = lane & 3, t2 = t4 * 2;
    const int tok0 = blockIdx.x * MTILE;
    const int mrow = warp * 16;

    // LDSM lane mapping
    const int bn = ((lane >> 4) << 3) + (lane & 7);
    const int kh = (lane >> 3) & 1;

    // cp mappings
    const int xrow = tid >> 3, xc4 = (tid & 7) * 4;   // x: 4 ops (rows +32p)

    // ---- issue phase-A chunks 0,1 ----
    #pragma unroll
    for (int kn = 0; kn < 2; kn++) {
        unsigned xd = sbase + OFF_XST + kn * XSTG + (xrow * XST_F + xc4) * 4;
        const float* xsrc = x + (size_t)(tok0 + xrow) * DDIM + kn * KC + xc4;
        #pragma unroll
        for (int p = 0; p < 4; p++)
            cp16(xd + p * 32 * XST_F * 4, xsrc + (size_t)p * 32 * DDIM);
        if (tid < 192) {
            int r = tid >> 2, sg = tid & 3;
            cp16(sbase + OFF_WST + kn * WSTAGE_B + (r * WDST + sg * 8) * 2,
                 g_gw + (size_t)r * DDIM + kn * KC + sg * 8);
        }
        cp_commit();
    }

    // ---- prologue: small precomputed arrays (overlap chunk flight) ----
    for (int i = tid; i < RDIM; i += THREADS) {
        sumgw_s[i] = g_sumgw[i]; cb_s[i] = g_cb[i]; c48_s[i] = g_c48[i];
    }
    for (int i = tid; i < RDIM * RDIM; i += THREADS) A48T_s[i] = g_A48T[i];
    float scale = __ldg(scale_p);

    // ---- phase A mainloop (race-free order) ----
    float acc[6][4];
    #pragma unroll
    for (int j = 0; j < 6; j++)
        #pragma unroll
        for (int q = 0; q < 4; q++) acc[j][q] = 0.f;
    float ps0 = 0.f, pss0 = 0.f, ps1 = 0.f, pss1 = 0.f;

    #pragma unroll 1
    for (int kc = 0; kc < NCH; kc++) {
        cp_wait<1>();        // chunk kc landed ({kc+1} may remain in flight)
        __syncthreads();     // publishes chunk kc; everyone done reading kc-1
        int kn = kc + 2;
        if (kn < NCH) {      // stage (kc+2)%3 == (kc-1)%3: safe after barrier
            int st = kn % NSTAGE;
            unsigned xd = sbase + OFF_XST + st * XSTG + (xrow * XST_F + xc4) * 4;
            const float* xsrc = x + (size_t)(tok0 + xrow) * DDIM + kn * KC + xc4;
            #pragma unroll
            for (int p = 0; p < 4; p++)
                cp16(xd + p * 32 * XST_F * 4, xsrc + (size_t)p * 32 * DDIM);
            if (tid < 192) {
                int r = tid >> 2, sg = tid & 3;
                cp16(sbase + OFF_WST + st * WSTAGE_B + (r * WDST + sg * 8) * 2,
                     g_gw + (size_t)r * DDIM + kn * KC + sg * 8);
            }
        }
        cp_commit();         // possibly empty -> wait<1> stays template-constant

        const float* xs = (const float*)(smem + OFF_XST + (kc % NSTAGE) * XSTG);
        const unsigned wb = sbase + OFF_WST + (kc % NSTAGE) * WSTAGE_B
                          + (bn * WDST + kh * 8) * 2;
        #pragma unroll
        for (int kk = 0; kk < 2; kk++) {
            int cb_ = kk * 16;
            float2 p00 = *(const float2*)(xs + (mrow + g) * XST_F + cb_ + t2);
            float2 p10 = *(const float2*)(xs + (mrow + g + 8) * XST_F + cb_ + t2);
            float2 p01 = *(const float2*)(xs + (mrow + g) * XST_F + cb_ + 8 + t2);
            float2 p11 = *(const float2*)(xs + (mrow + g + 8) * XST_F + cb_ + 8 + t2);
            ps0  += (p00.x + p00.y) + (p01.x + p01.y);
            pss0 += (p00.x * p00.x + p00.y * p00.y) + (p01.x * p01.x + p01.y * p01.y);
            ps1  += (p10.x + p10.y) + (p11.x + p11.y);
            pss1 += (p10.x * p10.x + p10.y * p10.y) + (p11.x * p11.x + p11.y * p11.y);
            unsigned a0 = pack2(p00.x, p00.y);
            unsigned a1 = pack2(p10.x, p10.y);
            unsigned a2 = pack2(p01.x, p01.y);
            unsigned a3 = pack2(p11.x, p11.y);

            unsigned br[3][4];
            #pragma unroll
            for (int p = 0; p < 3; p++)
                ldsm_x4(br[p], wb + p * 16 * WDST * 2 + cb_ * 2);
            #pragma unroll
            for (int j = 0; j < 6; j++)
                mma_bf16(acc[j], a0, a1, a2, a3,
                         br[j >> 1][(j & 1) * 2], br[j >> 1][(j & 1) * 2 + 1]);
        }
    }

    // ---- stats reduce over t4 lanes; LN params in registers ----
    #pragma unroll
    for (int off = 1; off <= 2; off <<= 1) {
        ps0  += __shfl_xor_sync(0xffffffffu, ps0, off);
        pss0 += __shfl_xor_sync(0xffffffffu, pss0, off);
        ps1  += __shfl_xor_sync(0xffffffffu, ps1, off);
        pss1 += __shfl_xor_sync(0xffffffffu, pss1, off);
    }
    float mu0 = ps0 * (1.0f / DDIM);
    float ri0 = rsqrtf(pss0 * (1.0f / DDIM) - mu0 * mu0 + 1e-5f);
    float mu1 = ps1 * (1.0f / DDIM);
    float ri1 = rsqrtf(pss1 * (1.0f / DDIM) - mu1 * mu1 + 1e-5f);

    cp_wait<0>();      // drain any tail groups
    __syncthreads();   // all phase-A stage reads done -> stages reusable

    // ---- prefetch phase-C chunks 0,1 (x residual + wu rows) ----
    #pragma unroll
    for (int nn = 0; nn < 2; nn++) {
        unsigned xd = sbase + OFF_XST + nn * XSTG + (xrow * XST_F + xc4) * 4;
        const float* xsrc = x + (size_t)(tok0 + xrow) * DDIM + nn * KC + xc4;
        #pragma unroll
        for (int p = 0; p < 4; p++)
            cp16(xd + p * 32 * XST_F * 4, xsrc + (size_t)p * 32 * DDIM);
        if (tid < 192) {
            int row = tid / 6, sg = tid % 6;
            cp16(sbase + OFF_WST + nn * WSTAGE_B + (row * WUST + sg * 8) * 2,
                 g_wu + (size_t)(nn * KC + row) * RDIM + sg * 8);
        }
        cp_commit();
    }

    // ---- y = gelu(rinv*(acc - mu*sumgw) + cb) -> bf16 ----
    {
        int r0 = mrow + g, r1 = r0 + 8;
        #pragma unroll
        for (int j = 0; j < 6; j++) {
            int c0 = j * 8 + t2, c1 = c0 + 1;
            float y00 = gelu_exact(ri0 * (acc[j][0] - mu0 * sumgw_s[c0]) + cb_s[c0]);
            float y01 = gelu_exact(ri0 * (acc[j][1] - mu0 * sumgw_s[c1]) + cb_s[c1]);
            float y10 = gelu_exact(ri1 * (acc[j][2] - mu1 * sumgw_s[c0]) + cb_s[c0]);
            float y11 = gelu_exact(ri1 * (acc[j][3] - mu1 * sumgw_s[c1]) + cb_s[c1]);
            *(__nv_bfloat162*)(y_s + r0 * YS_STRIDE + c0) = __floats2bfloat162_rn(y00, y01);
            *(__nv_bfloat162*)(y_s + r1 * YS_STRIDE + c0) = __floats2bfloat162_rn(y10, y11);
        }
    }
    __syncthreads();   // y visible

    // ---- middle: h2 = gelu(A48 @ y + c48) -> bf16 ----
    {
        int t = tid >> 1;                 // 0..127
        int rbase = (tid & 1) * 24;
        const __nv_bfloat16* yrow = y_s + t * YS_STRIDE;
        float h2v[24];
        #pragma unroll
        for (int r = 0; r < 24; r++) h2v[r] = c48_s[rbase + r];
        #pragma unroll 4
        for (int kp2 = 0; kp2 < RDIM / 2; kp2++) {
            __nv_bfloat162 yp = *(const __nv_bfloat162*)(yrow + kp2 * 2);
            float yv0 = __bfloat162float(yp.x), yv1 = __bfloat162float(yp.y);
            const float* a0 = A48T_s + (kp2 * 2) * RDIM + rbase;
            const float* a1 = a0 + RDIM;
            #pragma unroll
            for (int r = 0; r < 24; r++) h2v[r] += yv0 * a0[r] + yv1 * a1[r];
        }
        __nv_bfloat16* op = h2_s + t * H2_STRIDE + rbase;
        #pragma unroll
        for (int r = 0; r < 24; r += 2) {
            __nv_bfloat162 p = __floats2bfloat162_rn(gelu_exact(h2v[r]), gelu_exact(h2v[r + 1]));
            *(__nv_bfloat162*)(op + r) = p;
        }
    }
    __syncthreads();   // h2 visible

    // ---- phase C: out = x + scale*(h2 @ wu^T) ----
    unsigned afr[3][4];
    #pragma unroll
    for (int kk = 0; kk < 3; kk++) {
        afr[kk][0] = *(const unsigned*)(h2_s + (mrow + g) * H2_STRIDE + kk * 16 + t2);
        afr[kk][1] = *(const unsigned*)(h2_s + (mrow + g + 8) * H2_STRIDE + kk * 16 + t2);
        afr[kk][2] = *(const unsigned*)(h2_s + (mrow + g) * H2_STRIDE + kk * 16 + 8 + t2);
        afr[kk][3] = *(const unsigned*)(h2_s + (mrow + g + 8) * H2_STRIDE + kk * 16 + 8 + t2);
    }

    #pragma unroll 1
    for (int nc = 0; nc < NCH; nc++) {
        cp_wait<1>();        // chunk nc landed
        __syncthreads();     // publish + everyone done reading nc-1
        int nn = nc + 2;
        if (nn < NCH) {
            int st = nn % NSTAGE;
            unsigned xd = sbase + OFF_XST + st * XSTG + (xrow * XST_F + xc4) * 4;
            const float* xsrc = x + (size_t)(tok0 + xrow) * DDIM + nn * KC + xc4;
            #pragma unroll
            for (int p = 0; p < 4; p++)
                cp16(xd + p * 32 * XST_F * 4, xsrc + (size_t)p * 32 * DDIM);
            if (tid < 192) {
                int row = tid / 6, sg = tid % 6;
                cp16(sbase + OFF_WST + st * WSTAGE_B + (row * WUST + sg * 8) * 2,
                     g_wu + (size_t)(nn * KC + row) * RDIM + sg * 8);
            }
        }
        cp_commit();

        const float* xs = (const float*)(smem + OFF_XST + (nc % NSTAGE) * XSTG);
        const unsigned wub = sbase + OFF_WST + (nc % NSTAGE) * WSTAGE_B
                           + (bn * WUST + kh * 8) * 2;

        float uacc[4][4];
        #pragma unroll
        for (int j = 0; j < 4; j++)
            #pragma unroll
            for (int q = 0; q < 4; q++) uacc[j][q] = 0.f;

        #pragma unroll
        for (int kk = 0; kk < 3; kk++) {
            unsigned br[2][4];
            ldsm_x4(br[0], wub + kk * 32);
            ldsm_x4(br[1], wub + 16 * WUST * 2 + kk * 32);
            #pragma unroll
            for (int j = 0; j < 4; j++)
                mma_bf16(uacc[j], afr[kk][0], afr[kk][1], afr[kk][2], afr[kk][3],
                         br[j >> 1][(j & 1) * 2], br[j >> 1][(j & 1) * 2 + 1]);
        }
        size_t row0 = (size_t)(tok0 + mrow + g) * DDIM + nc * KC;
        size_t row1 = row0 + 8 * (size_t)DDIM;
        #pragma unroll
        for (int j = 0; j < 4; j++) {
            int lc = j * 8 + t2;
            float2 xv0 = *(const float2*)(xs + (mrow + g) * XST_F + lc);
            float2 xv1 = *(const float2*)(xs + (mrow + g + 8) * XST_F + lc);
            float2 o0 = make_float2(xv0.x + scale * uacc[j][0], xv0.y + scale * uacc[j][1]);
            float2 o1 = make_float2(xv1.x + scale * uacc[j][2], xv1.y + scale * uacc[j][3]);
            __stcs((float2*)(out + row0 + lc), o0);
            __stcs((float2*)(out + row1 + lc), o1);
        }
    }
}

extern "C" void kernel_launch(void* const* d_in, const int* in_sizes, int n_in,
                              void* d_out, int out_size) {
    const float* x         = (const float*)d_in[0];
    const float* gamma     = (const float*)d_in[1];
    const float* beta      = (const float*)d_in[2];
    const float* w_down    = (const float*)d_in[3];
    const float* w_to_mv   = (const float*)d_in[4];
    const float* w_equi    = (const float*)d_in[5];
    const float* b_equi    = (const float*)d_in[6];
    const float* w_from_mv = (const float*)d_in[7];
    const float* w_up      = (const float*)d_in[8];
    const float* scale     = (const float*)d_in[9];
    float* out = (float*)d_out;

    cudaFuncSetAttribute(fused_kernel, cudaFuncAttributeMaxDynamicSharedMemorySize, SMEM_TOTAL);
    prep_kernel<<<128, 256>>>(gamma, beta, w_down, w_to_mv, w_equi, b_equi, w_from_mv, w_up);
    fused_kernel<<<NCTAS, THREADS, SMEM_TOTAL>>>(x, scale, out);
}

// round 17
// speedup vs baseline: 1.0414x; 1.0414x over previous
#include <cuda_runtime.h>
#include <cuda_bf16.h>

#define TOKENS 32768
#define DDIM 1024
#define RDIM 48
#define MTILE 128
#define THREADS 256
#define NCTAS (TOKENS / MTILE)   // 256 CTAs, 2 per SM
#define KC 32
#define NCH (DDIM / KC)          // 32 chunks per phase
#define NSTAGE 4                 // depth-3 pipeline (3 chunks in flight)

#define XST_F 36                 // fp32 elems/row (144B)
#define WDST 40                  // bf16 elems/row (80B; ldsm conflict-free)
#define WUST 56                  // bf16 elems/row (112B; ldsm conflict-free)
#define YS_STRIDE 52             // bf16
#define H2_STRIDE 52             // bf16

#define XSTG (MTILE * XST_F * 4)         // 18432
#define WSTAGE_B (RDIM * WDST * 2)       // 3840 (>= wu stage 32*112=3584)

// ---- smem layout (bytes): 112192 total -> 2 CTAs/SM ----
// y overlays x-stage 3 (dead in the inter-phase window); h2 has its own region.
#define OFF_XST 0                                  // 4 x-stages: 73728
#define OFF_WST (OFF_XST + NSTAGE * XSTG)          // 4 w-stages: 15360
#define OFF_H2  (OFF_WST + NSTAGE * WSTAGE_B)      // 13312
#define OFF_A48 (OFF_H2 + MTILE * H2_STRIDE * 2)   // 9216
#define OFF_SGW (OFF_A48 + RDIM * RDIM * 4)        // 192
#define OFF_CB  (OFF_SGW + RDIM * 4)               // 192
#define OFF_C48 (OFF_CB + RDIM * 4)                // 192
#define SMEM_TOTAL (OFF_C48 + RDIM * 4)            // 112192 <= 116224
#define OFF_Y   (OFF_XST + 3 * XSTG)               // y overlays stage 3 (13312 <= 18432)

// ---- global scratch (prep output) ----
__device__ __align__(16) __nv_bfloat16 g_gw[RDIM * DDIM];   // gamma (*) w_down
__device__ __align__(16) __nv_bfloat16 g_wu[DDIM * RDIM];
__device__ float g_sumgw[RDIM];
__device__ float g_cb[RDIM];
__device__ float g_c48[RDIM];
__device__ float g_A48T[RDIM * RDIM];

__device__ __forceinline__ float gelu_exact(float v) {
    return 0.5f * v * (1.0f + erff(v * 0.70710678118654752440f));
}

__device__ __forceinline__ void mma_bf16(float* c, unsigned a0, unsigned a1, unsigned a2,
                                         unsigned a3, unsigned b0, unsigned b1) {
    asm volatile(
        "mma.sync.aligned.m16n8k16.row.col.f32.bf16.bf16.f32 "
        "{%0,%1,%2,%3}, {%4,%5,%6,%7}, {%8,%9}, {%0,%1,%2,%3};\n"
        : "+f"(c[0]), "+f"(c[1]), "+f"(c[2]), "+f"(c[3])
        : "r"(a0), "r"(a1), "r"(a2), "r"(a3), "r"(b0), "r"(b1));
}

__device__ __forceinline__ void ldsm_x4(unsigned* r, unsigned addr) {
    asm volatile("ldmatrix.sync.aligned.m8n8.x4.shared.b16 {%0,%1,%2,%3}, [%4];"
                 : "=r"(r[0]), "=r"(r[1]), "=r"(r[2]), "=r"(r[3]) : "r"(addr));
}

__device__ __forceinline__ unsigned pack2(float a, float b) {
    __nv_bfloat162 p = __floats2bfloat162_rn(a, b);
    return *(unsigned*)&p;
}
__device__ __forceinline__ uint2 pack_bf16x4(float a, float b, float c, float d) {
    uint2 pk;
    pk.x = pack2(a, b);
    pk.y = pack2(c, d);
    return pk;
}

__device__ __forceinline__ void cp16(unsigned dst, const void* src) {
    asm volatile("cp.async.cg.shared.global [%0], [%1], 16;\n" :: "r"(dst), "l"(src));
}
__device__ __forceinline__ void cp_commit() {
    asm volatile("cp.async.commit_group;\n");
}
template <int N>
__device__ __forceinline__ void cp_wait() {
    asm volatile("cp.async.wait_group %0;\n" :: "n"(N));
}

// ============================================================================
// prep: gamma-folded w_down -> bf16, w_up -> bf16, sumgw/cb, collapsed 48x48.
// ============================================================================
__global__ void prep_kernel(const float* __restrict__ gamma, const float* __restrict__ beta,
                            const float* __restrict__ w_down, const float* __restrict__ w_to_mv,
                            const float* __restrict__ w_equi, const float* __restrict__ b_equi,
                            const float* __restrict__ w_from_mv, const float* __restrict__ w_up) {
    int tid = threadIdx.x, lane = tid & 31;
    int gtid = blockIdx.x * blockDim.x + tid;
    int nth = gridDim.x * blockDim.x;
    int gwarp = gtid >> 5;

    if (gwarp < RDIM) {
        int r = gwarp;
        float s = 0.f, cb = 0.f;
        #pragma unroll
        for (int it = 0; it < 8; it++) {
            int d = it * 128 + lane * 4;
            float4 w  = *(const float4*)(w_down + (size_t)r * DDIM + d);
            float4 gv = *(const float4*)(gamma + d);
            float4 bv = *(const float4*)(beta + d);
            uint2 pk = pack_bf16x4(w.x * gv.x, w.y * gv.y, w.z * gv.z, w.w * gv.w);
            *(uint2*)(g_gw + (size_t)r * DDIM + d) = pk;
            __nv_bfloat162 b0 = *(__nv_bfloat162*)&pk.x;
            __nv_bfloat162 b1 = *(__nv_bfloat162*)&pk.y;
            s += __bfloat162float(b0.x) + __bfloat162float(b0.y)
               + __bfloat162float(b1.x) + __bfloat162float(b1.y);
            cb += w.x * bv.x + w.y * bv.y + w.z * bv.z + w.w * bv.w;
        }
        #pragma unroll
        for (int off = 16; off; off >>= 1) {
            s  += __shfl_xor_sync(0xffffffffu, s, off);
            cb += __shfl_xor_sync(0xffffffffu, cb, off);
        }
        if (lane == 0) { g_sumgw[r] = s; g_cb[r] = cb; }
    }
    for (int i = gtid; i < DDIM * RDIM / 4; i += nth) {
        float4 v = ((const float4*)w_up)[i];
        ((uint2*)g_wu)[i] = pack_bf16x4(v.x, v.y, v.z, v.w);
    }
    for (int i = gtid; i < RDIM * RDIM; i += nth) {
        int rp = i / RDIM, r = i - rp * RDIM;
        float a = 0.f;
        #pragma unroll
        for (int m = 0; m < 16; m++) {
            int gidx = (m == 0) ? 0 : (m < 5) ? 1 : (m < 11) ? 2 : (m < 15) ? 3 : 4;
            a += __ldg(w_from_mv + r * 16 + m) * __ldg(w_equi + gidx)
               * __ldg(w_to_mv + m * RDIM + rp);
        }
        g_A48T[i] = a;
    }
    for (int i = gtid; i < RDIM; i += nth)
        g_c48[i] = __ldg(w_from_mv + i * 16) * __ldg(b_equi);
}

// ============================================================================
// Fused kernel: 128-token tiles, 256 threads, 2 CTAs/SM, depth-3 cp.async
// pipeline (4 stages, wait<2>), race-free order wait -> sync -> issue -> consume.
// ============================================================================
__global__ void __launch_bounds__(THREADS, 2) fused_kernel(
    const float* __restrict__ x, const float* __restrict__ scale_p,
    float* __restrict__ out)
{
    extern __shared__ char smem[];
    const unsigned sbase = (unsigned)__cvta_generic_to_shared(smem);
    __nv_bfloat16* y_s  = (__nv_bfloat16*)(smem + OFF_Y);
    __nv_bfloat16* h2_s = (__nv_bfloat16*)(smem + OFF_H2);
    float* A48T_s  = (float*)(smem + OFF_A48);
    float* sumgw_s = (float*)(smem + OFF_SGW);
    float* cb_s    = (float*)(smem + OFF_CB);
    float* c48_s   = (float*)(smem + OFF_C48);

    const int tid = threadIdx.x, lane = tid & 31, warp = tid >> 5;
    const int g = lane >> 2, t4 = lane & 3, t2 = t4 * 2;
    const int tok0 = blockIdx.x * MTILE;
    const int mrow = warp * 16;

    // LDSM lane mapping
    const int bn = ((lane >> 4) << 3) + (lane & 7);
    const int kh = (lane >> 3) & 1;

    // cp mappings
    const int xrow = tid >> 3, xc4 = (tid & 7) * 4;   // x: 4 ops (rows +32p)

    // ---- issue phase-A chunks 0,1,2 ----
    #pragma unroll
    for (int kn = 0; kn < 3; kn++) {
        unsigned xd = sbase + OFF_XST + kn * XSTG + (xrow * XST_F + xc4) * 4;
        const float* xsrc = x + (size_t)(tok0 + xrow) * DDIM + kn * KC + xc4;
        #pragma unroll
        for (int p = 0; p < 4; p++)
            cp16(xd + p * 32 * XST_F * 4, xsrc + (size_t)p * 32 * DDIM);
        if (tid < 192) {
            int r = tid >> 2, sg = tid & 3;
            cp16(sbase + OFF_WST + kn * WSTAGE_B + (r * WDST + sg * 8) * 2,
                 g_gw + (size_t)r * DDIM + kn * KC + sg * 8);
        }
        cp_commit();
    }

    // ---- prologue: small precomputed arrays (overlap chunk flight) ----
    for (int i = tid; i < RDIM; i += THREADS) {
        sumgw_s[i] = g_sumgw[i]; cb_s[i] = g_cb[i]; c48_s[i] = g_c48[i];
    }
    for (int i = tid; i < RDIM * RDIM; i += THREADS) A48T_s[i] = g_A48T[i];
    float scale = __ldg(scale_p);

    // ---- phase A mainloop (race-free, depth 3) ----
    float acc[6][4];
    #pragma unroll
    for (int j = 0; j < 6; j++)
        #pragma unroll
        for (int q = 0; q < 4; q++) acc[j][q] = 0.f;
    float ps0 = 0.f, pss0 = 0.f, ps1 = 0.f, pss1 = 0.f;

    #pragma unroll 1
    for (int kc = 0; kc < NCH; kc++) {
        cp_wait<2>();        // chunk kc landed (kc+1, kc+2 may remain in flight)
        __syncthreads();     // publish kc; everyone done reading kc-1
        int kn = kc + 3;
        if (kn < NCH) {      // stage (kc+3)%4 == (kc-1)%4: safe after barrier
            int st = kn % NSTAGE;
            unsigned xd = sbase + OFF_XST + st * XSTG + (xrow * XST_F + xc4) * 4;
            const float* xsrc = x + (size_t)(tok0 + xrow) * DDIM + kn * KC + xc4;
            #pragma unroll
            for (int p = 0; p < 4; p++)
                cp16(xd + p * 32 * XST_F * 4, xsrc + (size_t)p * 32 * DDIM);
            if (tid < 192) {
                int r = tid >> 2, sg = tid & 3;
                cp16(sbase + OFF_WST + st * WSTAGE_B + (r * WDST + sg * 8) * 2,
                     g_gw + (size_t)r * DDIM + kn * KC + sg * 8);
            }
        }
        cp_commit();         // possibly empty -> wait<2> stays template-constant

        const float* xs = (const float*)(smem + OFF_XST + (kc % NSTAGE) * XSTG);
        const unsigned wb = sbase + OFF_WST + (kc % NSTAGE) * WSTAGE_B
                          + (bn * WDST + kh * 8) * 2;
        #pragma unroll
        for (int kk = 0; kk < 2; kk++) {
            int cb_ = kk * 16;
            float2 p00 = *(const float2*)(xs + (mrow + g) * XST_F + cb_ + t2);
            float2 p10 = *(const float2*)(xs + (mrow + g + 8) * XST_F + cb_ + t2);
            float2 p01 = *(const float2*)(xs + (mrow + g) * XST_F + cb_ + 8 + t2);
            float2 p11 = *(const float2*)(xs + (mrow + g + 8) * XST_F + cb_ + 8 + t2);
            ps0  += (p00.x + p00.y) + (p01.x + p01.y);
            pss0 += (p00.x * p00.x + p00.y * p00.y) + (p01.x * p01.x + p01.y * p01.y);
            ps1  += (p10.x + p10.y) + (p11.x + p11.y);
            pss1 += (p10.x * p10.x + p10.y * p10.y) + (p11.x * p11.x + p11.y * p11.y);
            unsigned a0 = pack2(p00.x, p00.y);
            unsigned a1 = pack2(p10.x, p10.y);
            unsigned a2 = pack2(p01.x, p01.y);
            unsigned a3 = pack2(p11.x, p11.y);

            unsigned br[3][4];
            #pragma unroll
            for (int p = 0; p < 3; p++)
                ldsm_x4(br[p], wb + p * 16 * WDST * 2 + cb_ * 2);
            #pragma unroll
            for (int j = 0; j < 6; j++)
                mma_bf16(acc[j], a0, a1, a2, a3,
                         br[j >> 1][(j & 1) * 2], br[j >> 1][(j & 1) * 2 + 1]);
        }
    }

    // ---- stats reduce over t4 lanes; LN params in registers ----
    #pragma unroll
    for (int off = 1; off <= 2; off <<= 1) {
        ps0  += __shfl_xor_sync(0xffffffffu, ps0, off);
        pss0 += __shfl_xor_sync(0xffffffffu, pss0, off);
        ps1  += __shfl_xor_sync(0xffffffffu, ps1, off);
        pss1 += __shfl_xor_sync(0xffffffffu, pss1, off);
    }
    float mu0 = ps0 * (1.0f / DDIM);
    float ri0 = rsqrtf(pss0 * (1.0f / DDIM) - mu0 * mu0 + 1e-5f);
    float mu1 = ps1 * (1.0f / DDIM);
    float ri1 = rsqrtf(pss1 * (1.0f / DDIM) - mu1 * mu1 + 1e-5f);

    cp_wait<0>();      // drain tail (empty) groups
    __syncthreads();   // all phase-A stage reads done -> all stages reusable

    // ---- y = gelu(rinv*(acc - mu*sumgw) + cb) -> bf16 (overlays stage 3) ----
    {
        int r0 = mrow + g, r1 = r0 + 8;
        #pragma unroll
        for (int j = 0; j < 6; j++) {
            int c0 = j * 8 + t2, c1 = c0 + 1;
            float y00 = gelu_exact(ri0 * (acc[j][0] - mu0 * sumgw_s[c0]) + cb_s[c0]);
            float y01 = gelu_exact(ri0 * (acc[j][1] - mu0 * sumgw_s[c1]) + cb_s[c1]);
            float y10 = gelu_exact(ri1 * (acc[j][2] - mu1 * sumgw_s[c0]) + cb_s[c0]);
            float y11 = gelu_exact(ri1 * (acc[j][3] - mu1 * sumgw_s[c1]) + cb_s[c1]);
            *(__nv_bfloat162*)(y_s + r0 * YS_STRIDE + c0) = __floats2bfloat162_rn(y00, y01);
            *(__nv_bfloat162*)(y_s + r1 * YS_STRIDE + c0) = __floats2bfloat162_rn(y10, y11);
        }
    }

    // ---- prefetch phase-C chunks 0,1,2 into stages 0,1,2 (x + wu) ----
    #pragma unroll
    for (int nn = 0; nn < 3; nn++) {
        unsigned xd = sbase + OFF_XST + nn * XSTG + (xrow * XST_F + xc4) * 4;
        const float* xsrc = x + (size_t)(tok0 + xrow) * DDIM + nn * KC + xc4;
        #pragma unroll
        for (int p = 0; p < 4; p++)
            cp16(xd + p * 32 * XST_F * 4, xsrc + (size_t)p * 32 * DDIM);
        if (tid < 192) {
            int row = tid / 6, sg = tid % 6;
            cp16(sbase + OFF_WST + nn * WSTAGE_B + (row * WUST + sg * 8) * 2,
                 g_wu + (size_t)(nn * KC + row) * RDIM + sg * 8);
        }
        cp_commit();
    }
    __syncthreads();   // y visible

    // ---- middle: h2 = gelu(A48 @ y + c48) -> bf16 (own region) ----
    {
        int t = tid >> 1;                 // 0..127
        int rbase = (tid & 1) * 24;
        const __nv_bfloat16* yrow = y_s + t * YS_STRIDE;
        float h2v[24];
        #pragma unroll
        for (int r = 0; r < 24; r++) h2v[r] = c48_s[rbase + r];
        #pragma unroll 4
        for (int kp2 = 0; kp2 < RDIM / 2; kp2++) {
            __nv_bfloat162 yp = *(const __nv_bfloat162*)(yrow + kp2 * 2);
            float yv0 = __bfloat162float(yp.x), yv1 = __bfloat162float(yp.y);
            const float* a0 = A48T_s + (kp2 * 2) * RDIM + rbase;
            const float* a1 = a0 + RDIM;
            #pragma unroll
            for (int r = 0; r < 24; r++) h2v[r] += yv0 * a0[r] + yv1 * a1[r];
        }
        __nv_bfloat16* op = h2_s + t * H2_STRIDE + rbase;
        #pragma unroll
        for (int r = 0; r < 24; r += 2) {
            __nv_bfloat162 p = __floats2bfloat162_rn(gelu_exact(h2v[r]), gelu_exact(h2v[r + 1]));
            *(__nv_bfloat162*)(op + r) = p;
        }
    }
    __syncthreads();   // h2 visible

    // ---- afr from h2 (then y/stage-3 may be overwritten by chunk 3) ----
    unsigned afr[3][4];
    #pragma unroll
    for (int kk = 0; kk < 3; kk++) {
        afr[kk][0] = *(const unsigned*)(h2_s + (mrow + g) * H2_STRIDE + kk * 16 + t2);
        afr[kk][1] = *(const unsigned*)(h2_s + (mrow + g + 8) * H2_STRIDE + kk * 16 + t2);
        afr[kk][2] = *(const unsigned*)(h2_s + (mrow + g) * H2_STRIDE + kk * 16 + 8 + t2);
        afr[kk][3] = *(const unsigned*)(h2_s + (mrow + g + 8) * H2_STRIDE + kk * 16 + 8 + t2);
    }
    __syncthreads();   // all warps read y (middle) and h2 (afr): stage 3 free

    // ---- phase C mainloop (race-free, depth 3) ----
    #pragma unroll 1
    for (int nc = 0; nc < NCH; nc++) {
        cp_wait<2>();        // chunk nc landed
        __syncthreads();     // publish nc; everyone done reading nc-1
        int nn = nc + 3;
        if (nn < NCH) {
            int st = nn % NSTAGE;
            unsigned xd = sbase + OFF_XST + st * XSTG + (xrow * XST_F + xc4) * 4;
            const float* xsrc = x + (size_t)(tok0 + xrow) * DDIM + nn * KC + xc4;
            #pragma unroll
            for (int p = 0; p < 4; p++)
                cp16(xd + p * 32 * XST_F * 4, xsrc + (size_t)p * 32 * DDIM);
            if (tid < 192) {
                int row = tid / 6, sg = tid % 6;
                cp16(sbase + OFF_WST + st * WSTAGE_B + (row * WUST + sg * 8) * 2,
                     g_wu + (size_t)(nn * KC + row) * RDIM + sg * 8);
            }
        }
        cp_commit();

        const float* xs = (const float*)(smem + OFF_XST + (nc % NSTAGE) * XSTG);
        const unsigned wub = sbase + OFF_WST + (nc % NSTAGE) * WSTAGE_B
                           + (bn * WUST + kh * 8) * 2;

        float uacc[4][4];
        #pragma unroll
        for (int j = 0; j < 4; j++)
            #pragma unroll
            for (int q = 0; q < 4; q++) uacc[j][q] = 0.f;

        #pragma unroll
        for (int kk = 0; kk < 3; kk++) {
            unsigned br[2][4];
            ldsm_x4(br[0], wub + kk * 32);
            ldsm_x4(br[1], wub + 16 * WUST * 2 + kk * 32);
            #pragma unroll
            for (int j = 0; j < 4; j++)
                mma_bf16(uacc[j], afr[kk][0], afr[kk][1], afr[kk][2], afr[kk][3],
                         br[j >> 1][(j & 1) * 2], br[j >> 1][(j & 1) * 2 + 1]);
        }
        size_t row0 = (size_t)(tok0 + mrow + g) * DDIM + nc * KC;
        size_t row1 = row0 + 8 * (size_t)DDIM;
        #pragma unroll
        for (int j = 0; j < 4; j++) {
            int lc = j * 8 + t2;
            float2 xv0 = *(const float2*)(xs + (mrow + g) * XST_F + lc);
            float2 xv1 = *(const float2*)(xs + (mrow + g + 8) * XST_F + lc);
            float2 o0 = make_float2(xv0.x + scale * uacc[j][0], xv0.y + scale * uacc[j][1]);
            float2 o1 = make_float2(xv1.x + scale * uacc[j][2], xv1.y + scale * uacc[j][3]);
            __stcs((float2*)(out + row0 + lc), o0);
            __stcs((float2*)(out + row1 + lc), o1);
        }
    }
}

extern "C" void kernel_launch(void* const* d_in, const int* in_sizes, int n_in,
                              void* d_out, int out_size) {
    const float* x         = (const float*)d_in[0];
    const float* gamma     = (const float*)d_in[1];
    const float* beta      = (const float*)d_in[2];
    const float* w_down    = (const float*)d_in[3];
    const float* w_to_mv   = (const float*)d_in[4];
    const float* w_equi    = (const float*)d_in[5];
    const float* b_equi    = (const float*)d_in[6];
    const float* w_from_mv = (const float*)d_in[7];
    const float* w_up      = (const float*)d_in[8];
    const float* scale     = (const float*)d_in[9];
    float* out = (float*)d_out;

    cudaFuncSetAttribute(fused_kernel, cudaFuncAttributeMaxDynamicSharedMemorySize, SMEM_TOTAL);
    prep_kernel<<<128, 256>>>(gamma, beta, w_down, w_to_mv, w_equi, b_equi, w_from_mv, w_up);
    fused_kernel<<<NCTAS, THREADS, SMEM_TOTAL>>>(x, scale, out);
}